// round 5
// baseline (speedup 1.0000x reference)
#include <cuda_runtime.h>
#include <math.h>
#include <stdint.h>

// ---------------- problem constants ----------------
#define NN   2048
#define NT   512
#define BB   8
#define KK   4
#define BK   32
#define QN   (NN / KK)          // 512 elements per cluster-rank quarter
#define TWO_PI_F 6.283185307179586f

// output layout (flattened tuple, fp32)
#define OUT_EIF 0
#define OUT_XM  65536
#define OUT_YM  131072
#define OUT_BSX 196608
#define OUT_BSY 212992
#define OUT_LAM 229376
#define OUT_SC  245760

// ---------------- barrier helpers ----------------
template<int GSIZE>
__device__ __forceinline__ void barx(int barId)
{
    if (GSIZE == NT) __syncthreads();
    else asm volatile("bar.sync %0, %1;" :: "r"(barId), "r"(GSIZE) : "memory");
}

// single-value group reduce: shuffle chain -> partials -> one barrier -> all sum
template<int GSIZE>
__device__ __forceinline__ float gred1(float v, volatile float* sred, int gtid, int barId)
{
#pragma unroll
    for (int o = 16; o > 0; o >>= 1) v += __shfl_down_sync(0xffffffffu, v, o);
    if ((gtid & 31) == 0) sred[gtid >> 5] = v;
    barx<GSIZE>(barId);
    float s = 0.f;
#pragma unroll
    for (int j = 0; j < GSIZE / 32; j++) s += sred[j];
    return s;
}

// pentadiagonal stencil of (D^T D); window w[k] maps to element (base-2+k).
__device__ __forceinline__ float sten(const float* w, int c, int i)
{
    if (i == 0)        return 2.f*w[c+2] - 3.f*w[c+3] + w[c+4];
    if (i == 1)        return -3.f*w[c+1] + 6.f*w[c+2] - 4.f*w[c+3] + w[c+4];
    if (i == NN-2)     return w[c] - 4.f*w[c+1] + 6.f*w[c+2] - 3.f*w[c+3];
    if (i == NN-1)     return w[c] - 3.f*w[c+1] + 2.f*w[c+2];
    return w[c] - 4.f*w[c+1] + 6.f*w[c+2] - 4.f*w[c+3] + w[c+4];
}

// CG with reference semantics: explicit rsnew = ||r - a*Ap||^2 (computed from
// the actually-updated r), freeze == break (state frozen forever after done).
// p kept in registers; only r halo values (4 per thread) go through SMEM, and
// neighbor p halos are reconstructed as r_halo + beta * p_halo_old.
// sp points at element 0 of an [NN] view with 2 guard floats each side (guard
// VALUES are never used by the boundary stencil formulas).
// 2 barriers per iteration (the two reduction barriers).
template<int GSIZE, int NPT>
__device__ __forceinline__ void cg_solve(int gtid, int barId, float coef,
        const float* d, float* x, const float* rhs,
        float* sp, volatile float* sA, volatile float* sB, bool x0_zero)
{
    const int base = gtid * NPT;
    float r[NPT], p[NPT];
    float rl = 0.f;

    barx<GSIZE>(barId);                    // prior readers of sp region done
    if (x0_zero) {
#pragma unroll
        for (int c = 0; c < NPT; c++) { r[c] = rhs[c]; rl += r[c] * r[c]; }
    } else {
        sp[base] = x[0]; sp[base + 1] = x[1];
        sp[base + NPT - 2] = x[NPT - 2]; sp[base + NPT - 1] = x[NPT - 1];
        barx<GSIZE>(barId);
        float w[NPT + 4];
        w[0] = sp[base - 2]; w[1] = sp[base - 1];
        w[NPT + 2] = sp[base + NPT]; w[NPT + 3] = sp[base + NPT + 1];
#pragma unroll
        for (int c = 0; c < NPT; c++) w[c + 2] = x[c];
#pragma unroll
        for (int c = 0; c < NPT; c++) {
            float Ax = coef * sten(w, c, base + c) + d[c] * x[c];
            r[c] = rhs[c] - Ax;
            rl += r[c] * r[c];
        }
        barx<GSIZE>(barId);                // x-halo reads done before overwrite
    }
    // publish r halos (p = r initially), reduce rs
    sp[base] = r[0]; sp[base + 1] = r[1];
    sp[base + NPT - 2] = r[NPT - 2]; sp[base + NPT - 1] = r[NPT - 1];
    float rs = gred1<GSIZE>(rl, sB, gtid, barId);
    float hl0 = sp[base - 2], hl1 = sp[base - 1];
    float hr0 = sp[base + NPT], hr1 = sp[base + NPT + 1];
#pragma unroll
    for (int c = 0; c < NPT; c++) p[c] = r[c];

    for (int it = 0; it < 30; it++) {
        float w[NPT + 4];
        w[0] = hl0; w[1] = hl1; w[NPT + 2] = hr0; w[NPT + 3] = hr1;
#pragma unroll
        for (int c = 0; c < NPT; c++) w[c + 2] = p[c];
        float Ap[NPT];
        float pl = 0.f;
#pragma unroll
        for (int c = 0; c < NPT; c++) {
            Ap[c] = coef * sten(w, c, base + c) + d[c] * p[c];
            pl += p[c] * Ap[c];
        }
        float pAp = gred1<GSIZE>(pl, sA, gtid, barId);        // barrier 1
        float a = rs / (pAp + 1e-12f);
        float rl2 = 0.f;
#pragma unroll
        for (int c = 0; c < NPT; c++) {
            x[c] += a * p[c];
            r[c] -= a * Ap[c];
            rl2 += r[c] * r[c];
        }
        // publish new r halos before the rsnew barrier
        sp[base] = r[0]; sp[base + 1] = r[1];
        sp[base + NPT - 2] = r[NPT - 2]; sp[base + NPT - 1] = r[NPT - 1];
        float rsnew = gred1<GSIZE>(rl2, sB, gtid, barId);      // barrier 2
        if (sqrtf(rsnew) < 1e-6f) break;    // uniform across group; == freeze
        float bta = rsnew / (rs + 1e-12f);
        float nl0 = sp[base - 2], nl1 = sp[base - 1];
        float nr0 = sp[base + NPT], nr1 = sp[base + NPT + 1];
#pragma unroll
        for (int c = 0; c < NPT; c++) p[c] = r[c] + bta * p[c];
        hl0 = nl0 + bta * hl0; hl1 = nl1 + bta * hl1;
        hr0 = nr0 + bta * hr0; hr1 = nr1 + bta * hr1;
        rs = rsnew;
    }
}

// fast phase scan: full block, 4 contiguous elems/thread, y must be 16B aligned.
__device__ __forceinline__ void fast_phase(const float* __restrict__ y, float halfdx,
                                           volatile float* wsum, float ph4[4])
{
    int tid = threadIdx.x;
    int lane = tid & 31, wi = tid >> 5;
    int base = tid * 4;
    float4 y4 = *reinterpret_cast<const float4*>(y + base);
    float a0 = 0.f;
    if (base > 0) a0 = (y[base - 1] + y4.x) * halfdx;
    float s0 = a0;
    float s1 = s0 + (y4.x + y4.y) * halfdx;
    float s2 = s1 + (y4.y + y4.z) * halfdx;
    float s3 = s2 + (y4.z + y4.w) * halfdx;
    float tot = s3, v = tot;
#pragma unroll
    for (int o = 1; o < 32; o <<= 1) {
        float n = __shfl_up_sync(0xffffffffu, v, o);
        if (lane >= o) v += n;
    }
    __syncthreads();                 // protect wsum reuse + prior y stores read
    if (lane == 31) wsum[wi] = v;
    __syncthreads();
    float off = 0.f;
    for (int j = 0; j < wi; j++) off += wsum[j];
    float excl = off + v - tot;
    ph4[0] = TWO_PI_F * (excl + s0);
    ph4[1] = TWO_PI_F * (excl + s1);
    ph4[2] = TWO_PI_F * (excl + s2);
    ph4[3] = TWO_PI_F * (excl + s3);
}

// DSMEM scalar load from cluster rank `rk`
__device__ __forceinline__ float dsmem_ldf(const float* ptr, int rk)
{
    uint32_t a = (uint32_t)__cvta_generic_to_shared(ptr);
    uint32_t ra; float v;
    asm volatile("mapa.shared::cluster.u32 %0, %1, %2;" : "=r"(ra) : "r"(a), "r"(rk));
    asm volatile("ld.shared::cluster.f32 %0, [%1];" : "=f"(v) : "r"(ra) : "memory");
    return v;
}

// ================= ONE fused kernel (cluster of 4 CTAs = one batch) =========
__global__ __launch_bounds__(NT, 1) __cluster_dims__(KK, 1, 1)
void fused_kernel(
    const float* __restrict__ s_in, const float* __restrict__ eIF,
    const float* __restrict__ xm, const float* __restrict__ ym,
    const float* __restrict__ sumx, const float* __restrict__ sumy,
    const float* __restrict__ lam, const int* __restrict__ mask,
    const float* __restrict__ initf,
    const float* __restrict__ alpha_p, const float* __restrict__ beta_p,
    const float* __restrict__ var_p, const float* __restrict__ fs_p,
    const int* __restrict__ iter_p,
    const float* __restrict__ fe_w1, const float* __restrict__ fe_b1,
    const float* __restrict__ fe_w2, const float* __restrict__ fe_b2,
    const float* __restrict__ pr_w1, const float* __restrict__ pr_b1,
    const float* __restrict__ pr_w2, const float* __restrict__ pr_b2,
    const float* __restrict__ pr_w3, const float* __restrict__ pr_b3,
    const float* __restrict__ iw_p,
    float* __restrict__ d_out)
{
    // buffers (raw index [0,NN) at +0; CG p-views use +2 with 2 guards each side)
    __shared__ __align__(16) float sbuf0[NN + 4];  // cos -> sp_x -> sp_smooth -> cx
    __shared__ __align__(16) float sbuf1[NN + 4];  // sin -> sp_y -> newEIF -> cy
    __shared__ __align__(16) float brx[NN];        // rhsx -> xs
    __shared__ __align__(16) float bry[NN];        // rhsy -> ys
    __shared__ __align__(16) float u_buf[NN];
    __shared__ float sredA[2][16];
    __shared__ float sredB[2][16];
    __shared__ float wsum[16];
    __shared__ float m_avg[BB];
    __shared__ float m_h1[BB*32];
    __shared__ float m_z0[BB*18];
    __shared__ float m_z1[BB*64];
    __shared__ float m_z2[BB*32];
    __shared__ float m_res[BB*2];
    __shared__ float m_scal[4];

    const int bk  = blockIdx.x;
    const int b   = bk >> 2;
    const int rk  = bk & 3;          // cluster rank
    const int tid = threadIdx.x;
    const float alpha = *alpha_p, beta = *beta_p;

    // ---------- MLP (recomputed per CTA; identical everywhere) ----------
    if (tid < BB) {
        const float* f = initf + tid * KK;
        m_avg[tid] = (((f[0] + f[1]) + f[2]) + f[3]) * 0.25f;
    }
    __syncthreads();
    if (tid < 256) {
        int bb = tid >> 5, j = tid & 31;
        m_h1[bb*32 + j] = fmaxf(0.f, m_avg[bb] * fe_w1[j] + fe_b1[j]);
    }
    __syncthreads();
    if (tid < 128) {
        int bb = tid >> 4, j = tid & 15;
        float acc = fe_b2[j];
        for (int e = 0; e < 32; e++) acc += m_h1[bb*32 + e] * fe_w2[j*32 + e];
        m_z0[bb*18 + j] = fmaxf(0.f, acc);
    }
    if (tid < BB) { m_z0[tid*18 + 16] = alpha; m_z0[tid*18 + 17] = beta; }
    __syncthreads();
    {
        int bb = tid >> 6, j = tid & 63;
        float acc = pr_b1[j];
        for (int e = 0; e < 18; e++) acc += m_z0[bb*18 + e] * pr_w1[j*18 + e];
        m_z1[bb*64 + j] = fmaxf(0.f, acc);
    }
    __syncthreads();
    if (tid < 256) {
        int bb = tid >> 5, j = tid & 31;
        float acc = pr_b2[j];
        for (int e = 0; e < 64; e++) acc += m_z1[bb*64 + e] * pr_w2[j*64 + e];
        m_z2[bb*32 + j] = fmaxf(0.f, acc);
    }
    __syncthreads();
    if (tid < 16) {
        int bb = tid >> 1, j = tid & 1;
        float acc = pr_b3[j];
        for (int e = 0; e < 32; e++) acc += m_z2[bb*32 + e] * pr_w3[j*32 + e];
        m_res[bb*2 + j] = tanhf(acc);
    }
    __syncthreads();
    if (tid == 0) {
        float iw = *iw_p;
        int it = *iter_p;
        float fac = 1.f / (1.f + expf(-iw * (float)it));
        float m0 = 0.f, m1 = 0.f;
        for (int bb = 0; bb < BB; bb++) {
            m0 += (m_res[bb*2 + 0] * fac * 0.1f) * alpha;
            m1 += (m_res[bb*2 + 1] * fac * 0.1f) * beta;
        }
        m0 *= 0.125f; m1 *= 0.125f;
        float na = fminf(fmaxf(alpha + m0, 1e-6f), 0.01f);
        float nb = fminf(fmaxf(beta  + m1, 1e-6f), 0.1f);
        double bt = pow(10.0, (double)it / 36.0 - 10.0);
        float betathr = fminf((float)bt, nb);
        m_scal[0] = na; m_scal[1] = nb;
        m_scal[2] = 2.f / na; m_scal[3] = 2.f / betathr;
        if (bk == 0) { d_out[OUT_SC + 0] = na; d_out[OUT_SC + 1] = nb; }
    }
    __syncthreads();
    const float na = m_scal[0];
    const float coefA = m_scal[2];
    const float coefS = m_scal[3];
    const float dxf = 1.0f / (*fs_p);
    const float halfdx = 0.5f * dxf;

    // ---------- u = projec5(...) ----------
    const int base4 = tid * 4;
    const int bbase = b * NN + base4;
    float4 sv = *reinterpret_cast<const float4*>(s_in + bbase);
    float4 sx = *reinterpret_cast<const float4*>(sumx + bbase);
    float4 sy = *reinterpret_cast<const float4*>(sumy + bbase);
    float4 lv = *reinterpret_cast<const float4*>(lam  + bbase);
    float uv[4];
    uv[0] = sv.x - sx.x - sy.x - lv.x / na;
    uv[1] = sv.y - sx.y - sy.y - lv.y / na;
    uv[2] = sv.z - sx.z - sy.z - lv.z / na;
    uv[3] = sv.w - sx.w - sy.w - lv.w / na;
    {
        float loc = uv[0]*uv[0] + uv[1]*uv[1] + uv[2]*uv[2] + uv[3]*uv[3];
        float n2 = gred1<NT>(loc, sredA[0], tid, 0);
        float n = sqrtf(n2);
        float e = sqrtf((float)NN * (*var_p));
        float scale = (n > e) ? (e / fmaxf(n, 1e-30f)) : 1.f;
#pragma unroll
        for (int c = 0; c < 4; c++) { uv[c] *= scale; u_buf[base4 + c] = uv[c]; }
    }

    // ---------- phase + rhs (store to SMEM only) ----------
    {
        float ph4[4];
        fast_phase(eIF + bk * NN, halfdx, wsum, ph4);
        const int rbase = bk * NN + base4;
#pragma unroll
        for (int c = 0; c < 4; c++) {
            float ssn, ccs;
            sincosf(ph4[c], &ssn, &ccs);
            float xv = xm[rbase + c], yv = ym[rbase + c];
            float resid = ((const float*)&sv.x)[c]
                        - (((const float*)&sx.x)[c] - xv * ccs)
                        - (((const float*)&sy.x)[c] - yv * ssn)
                        - uv[c]
                        - ((const float*)&lv.x)[c] / na;
            sbuf0[base4 + c] = ccs;
            sbuf1[base4 + c] = ssn;
            brx[base4 + c] = ccs * resid;
            bry[base4 + c] = ssn * resid;
        }
    }
    __syncthreads();

    // ---------- concurrent CG for x (warps 0-7) and y (warps 8-15) ----------
    {
        const int grp = tid >> 8;
        const int gtid = tid & 255;
        const int barId = 1 + grp;
        const float* trig = grp ? sbuf1 : sbuf0;
        const float* rh   = grp ? bry   : brx;
        const float* x0g  = (grp ? ym : xm) + bk * NN;
        float* sp         = (grp ? sbuf1 : sbuf0) + 2;     // halo-exchange view
        float* outb       = grp ? bry : brx;

        float d8[8], rhs8[8], x8[8];
#pragma unroll
        for (int c = 0; c < 8; c++) {
            int i = gtid * 8 + c;
            float t = trig[i];
            d8[c] = t * t + 1e-6f;
            rhs8[c] = rh[i];
            x8[c] = x0g[i];
        }
        cg_solve<256, 8>(gtid, barId, coefA, d8, x8, rhs8, sp,
                         sredA[grp], sredB[grp], false);
        // write result over rhs buffer (only this group reads/writes it)
        barx<256>(barId);
#pragma unroll
        for (int c = 0; c < 8; c++) outb[gtid * 8 + c] = x8[c];
    }
    __syncthreads();

    // ---------- deltaIF + smooth CG ----------
    float xv4[4], yv4[4], x4[4];
    {
        float rhs4[4], d4[4];
#pragma unroll
        for (int c = 0; c < 4; c++) {
            int i = base4 + c;
            float xb, yb;
            if (i == 0) {
                xb = (brx[1] - brx[0]) / dxf;
                yb = (bry[1] - bry[0]) / dxf;
            } else if (i == NN - 1) {
                xb = (brx[NN-1] - brx[NN-2]) / dxf;
                yb = (bry[NN-1] - bry[NN-2]) / dxf;
            } else {
                xb = (brx[i+1] - brx[i-1]) / (2.0f * dxf);
                yb = (bry[i+1] - bry[i-1]) / (2.0f * dxf);
            }
            xv4[c] = brx[i]; yv4[c] = bry[i];
            float denom = xv4[c]*xv4[c] + yv4[c]*yv4[c] + 1e-12f;
            rhs4[c] = (xv4[c] * yb - yv4[c] * xb) / (denom * TWO_PI_F);
            d4[c] = 1.0f + 1e-6f;
            x4[c] = 0.f;
        }
        cg_solve<NT, 4>(tid, 0, coefS, d4, x4, rhs4, sbuf0 + 2,
                        sredA[0], sredB[0], true);
    }

    // ---------- outputs eIF/xm/ym + stash new_eIF for phase scan ----------
    const bool act = (mask[bk] != 0);
    float ne4[4];
#pragma unroll
    for (int c = 0; c < 4; c++) {
        int i = base4 + c;
        int gi = bk * NN + i;
        float e = eIF[gi];
        ne4[c] = act ? (e - 0.5f * x4[c]) : e;
        d_out[OUT_EIF + gi] = ne4[c];
        d_out[OUT_XM  + gi] = act ? xv4[c] : xm[gi];
        d_out[OUT_YM  + gi] = act ? yv4[c] : ym[gi];
        sbuf1[i] = ne4[c];
    }
    __syncthreads();

    // ---------- new phase + masked contributions into SMEM ----------
    {
        float ph4[4];
        fast_phase(sbuf1, halfdx, wsum, ph4);   // internal syncs make reads safe
        float cx[4], cy[4];
#pragma unroll
        for (int c = 0; c < 4; c++) {
            float ssn, ccs;
            sincosf(ph4[c], &ssn, &ccs);
            cx[c] = act ? xv4[c] * ccs : 0.f;
            cy[c] = act ? yv4[c] * ssn : 0.f;
        }
        __syncthreads();        // all fast_phase reads of sbuf1 complete
#pragma unroll
        for (int c = 0; c < 4; c++) {
            sbuf0[base4 + c] = cx[c];
            sbuf1[base4 + c] = cy[c];
        }
    }

    // ---------- cluster gather: bsx/bsy + lamuda ----------
    asm volatile("barrier.cluster.arrive.aligned;" ::: "memory");
    asm volatile("barrier.cluster.wait.aligned;"   ::: "memory");
    {
        int i = rk * QN + tid;
        float bsx = 0.f, bsy = 0.f;
#pragma unroll
        for (int k = 0; k < KK; k++) {
            bsx += dsmem_ldf(&sbuf0[i], k);
            bsy += dsmem_ldf(&sbuf1[i], k);
        }
        int gi = b * NN + i;
        d_out[OUT_BSX + gi] = bsx;
        d_out[OUT_BSY + gi] = bsy;
        d_out[OUT_LAM + gi] = lam[gi] + na * (u_buf[i] + bsx + bsy - s_in[gi]);
    }
    asm volatile("barrier.cluster.arrive.aligned;" ::: "memory");
    asm volatile("barrier.cluster.wait.aligned;"   ::: "memory");
}

// ---------------- launch ---------------------------------------------------
extern "C" void kernel_launch(void* const* d_in, const int* in_sizes, int n_in,
                              void* d_out_v, int out_size)
{
    const float* s      = (const float*)d_in[0];
    const float* eIF    = (const float*)d_in[1];
    const float* xm     = (const float*)d_in[2];
    const float* ym     = (const float*)d_in[3];
    const float* sum_x  = (const float*)d_in[4];
    const float* sum_y  = (const float*)d_in[5];
    const float* lamuda = (const float*)d_in[6];
    const float* initf  = (const float*)d_in[7];
    const int*   mmask  = (const int*)  d_in[8];
    const float* alpha  = (const float*)d_in[9];
    const float* beta   = (const float*)d_in[10];
    const float* var    = (const float*)d_in[11];
    const float* fs     = (const float*)d_in[12];
    const int*   iter   = (const int*)  d_in[13];
    const float* fe_w1  = (const float*)d_in[14];
    const float* fe_b1  = (const float*)d_in[15];
    const float* fe_w2  = (const float*)d_in[16];
    const float* fe_b2  = (const float*)d_in[17];
    const float* pr_w1  = (const float*)d_in[18];
    const float* pr_b1  = (const float*)d_in[19];
    const float* pr_w2  = (const float*)d_in[20];
    const float* pr_b2  = (const float*)d_in[21];
    const float* pr_w3  = (const float*)d_in[22];
    const float* pr_b3  = (const float*)d_in[23];
    const float* iw     = (const float*)d_in[24];
    float* d_out = (float*)d_out_v;

    fused_kernel<<<BK, NT>>>(s, eIF, xm, ym, sum_x, sum_y, lamuda, mmask,
                             initf, alpha, beta, var, fs, iter,
                             fe_w1, fe_b1, fe_w2, fe_b2,
                             pr_w1, pr_b1, pr_w2, pr_b2, pr_w3, pr_b3,
                             iw, d_out);
}

// round 7
// speedup vs baseline: 1.0203x; 1.0203x over previous
#include <cuda_runtime.h>
#include <math.h>
#include <stdint.h>

// ---------------- problem constants ----------------
#define NN   2048
#define NT   512
#define BB   8
#define KK   4
#define BK   32
#define QN   (NN / KK)          // 512 elements per cluster-rank quarter
#define TWO_PI_F 6.283185307179586f

// output layout (flattened tuple, fp32)
#define OUT_EIF 0
#define OUT_XM  65536
#define OUT_YM  131072
#define OUT_BSX 196608
#define OUT_BSY 212992
#define OUT_LAM 229376
#define OUT_SC  245760

// ---------------- barrier helpers ----------------
template<int GSIZE>
__device__ __forceinline__ void barx(int barId)
{
    if (GSIZE == NT) __syncthreads();
    else asm volatile("bar.sync %0, %1;" :: "r"(barId), "r"(GSIZE) : "memory");
}

// group reduce, short shuffle chain:
//  GSIZE=256: 3 shuffles (8-lane groups) -> 32 partials
//  GSIZE=512: 4 shuffles (16-lane groups) -> 32 partials
// one barrier; every thread sums 32 partials via 8x float4.
template<int GSIZE>
__device__ __forceinline__ float gred1(float v, float* sred, int gtid, int barId)
{
    if (GSIZE == 256) {
#pragma unroll
        for (int o = 4; o > 0; o >>= 1) v += __shfl_down_sync(0xffffffffu, v, o);
        if ((gtid & 7) == 0) sred[gtid >> 3] = v;
    } else {
#pragma unroll
        for (int o = 8; o > 0; o >>= 1) v += __shfl_down_sync(0xffffffffu, v, o);
        if ((gtid & 15) == 0) sred[gtid >> 4] = v;
    }
    barx<GSIZE>(barId);
    float4 q0 = reinterpret_cast<float4*>(sred)[0];
    float4 q1 = reinterpret_cast<float4*>(sred)[1];
    float4 q2 = reinterpret_cast<float4*>(sred)[2];
    float4 q3 = reinterpret_cast<float4*>(sred)[3];
    float4 q4 = reinterpret_cast<float4*>(sred)[4];
    float4 q5 = reinterpret_cast<float4*>(sred)[5];
    float4 q6 = reinterpret_cast<float4*>(sred)[6];
    float4 q7 = reinterpret_cast<float4*>(sred)[7];
    float s0 = (q0.x + q0.y) + (q0.z + q0.w);
    float s1 = (q1.x + q1.y) + (q1.z + q1.w);
    float s2 = (q2.x + q2.y) + (q2.z + q2.w);
    float s3 = (q3.x + q3.y) + (q3.z + q3.w);
    float s4 = (q4.x + q4.y) + (q4.z + q4.w);
    float s5 = (q5.x + q5.y) + (q5.z + q5.w);
    float s6 = (q6.x + q6.y) + (q6.z + q6.w);
    float s7 = (q7.x + q7.y) + (q7.z + q7.w);
    return ((s0 + s1) + (s2 + s3)) + ((s4 + s5) + (s6 + s7));
}

// interior 5-point stencil of (D^T D): [1,-4,6,-4,1]; w[k] = elem(base-2+k)
#define STEN5(w, c) ((w)[c] - 4.f*(w)[(c)+1] + 6.f*(w)[(c)+2] - 4.f*(w)[(c)+3] + (w)[(c)+4])

// Boundary rows, exact reference expressions, recomputed on edge threads only.
template<int NPT>
__device__ __forceinline__ void fix_bounds(float coef, const float* d,
                                           const float* v, float* Av,
                                           bool isF, bool isL)
{
    if (isF) {
        Av[0] = coef * (2.f*v[0] - 3.f*v[1] + v[2]) + d[0]*v[0];
        Av[1] = coef * (-3.f*v[0] + 6.f*v[1] - 4.f*v[2] + v[3]) + d[1]*v[1];
    }
    if (isL) {
        Av[NPT-2] = coef * (v[NPT-4] - 4.f*v[NPT-3] + 6.f*v[NPT-2] - 3.f*v[NPT-1])
                  + d[NPT-2]*v[NPT-2];
        Av[NPT-1] = coef * (v[NPT-3] - 3.f*v[NPT-2] + 2.f*v[NPT-1])
                  + d[NPT-1]*v[NPT-1];
    }
}

// CG with reference semantics: explicit rsnew = ||r - a*Ap||^2, freeze == break.
// p in registers; r halos exchanged through SMEM (float2); neighbor p halos
// reconstructed as r_halo + beta*p_halo_old. sp = element-0 view with 2 guard
// floats each side (zeroed; never used in boundary math).
// 2 barriers per iteration.
template<int GSIZE, int NPT>
__device__ __forceinline__ void cg_solve(int gtid, int barId, float coef,
        const float* d, float* x, const float* rhs,
        float* sp, float* sA, float* sB, bool x0_zero)
{
    const int base = gtid * NPT;
    const bool isF = (gtid == 0);
    const bool isL = (gtid == GSIZE - 1);
    float r[NPT], p[NPT];
    float rl = 0.f;

    barx<GSIZE>(barId);                    // prior readers of sp region done
    if (isF) *reinterpret_cast<float2*>(sp - 2)  = make_float2(0.f, 0.f);
    if (isL) *reinterpret_cast<float2*>(sp + NN) = make_float2(0.f, 0.f);

    if (x0_zero) {
#pragma unroll
        for (int c = 0; c < NPT; c++) { r[c] = rhs[c]; rl += r[c] * r[c]; }
    } else {
        *reinterpret_cast<float2*>(sp + base)           = make_float2(x[0], x[1]);
        *reinterpret_cast<float2*>(sp + base + NPT - 2) = make_float2(x[NPT-2], x[NPT-1]);
        barx<GSIZE>(barId);
        float2 L = *reinterpret_cast<const float2*>(sp + base - 2);
        float2 R = *reinterpret_cast<const float2*>(sp + base + NPT);
        float w[NPT + 4];
        w[0] = L.x; w[1] = L.y; w[NPT + 2] = R.x; w[NPT + 3] = R.y;
#pragma unroll
        for (int c = 0; c < NPT; c++) w[c + 2] = x[c];
        float Ax[NPT];
#pragma unroll
        for (int c = 0; c < NPT; c++) Ax[c] = coef * STEN5(w, c) + d[c] * x[c];
        fix_bounds<NPT>(coef, d, x, Ax, isF, isL);
#pragma unroll
        for (int c = 0; c < NPT; c++) { r[c] = rhs[c] - Ax[c]; rl += r[c] * r[c]; }
        barx<GSIZE>(barId);                // x-halo reads done before overwrite
    }
    // publish r halos (p = r initially), reduce rs
    *reinterpret_cast<float2*>(sp + base)           = make_float2(r[0], r[1]);
    *reinterpret_cast<float2*>(sp + base + NPT - 2) = make_float2(r[NPT-2], r[NPT-1]);
    float rs = gred1<GSIZE>(rl, sB, gtid, barId);
    float2 Li = *reinterpret_cast<const float2*>(sp + base - 2);
    float2 Ri = *reinterpret_cast<const float2*>(sp + base + NPT);
    float hl0 = Li.x, hl1 = Li.y, hr0 = Ri.x, hr1 = Ri.y;
#pragma unroll
    for (int c = 0; c < NPT; c++) p[c] = r[c];

    for (int it = 0; it < 30; it++) {
        float w[NPT + 4];
        w[0] = hl0; w[1] = hl1; w[NPT + 2] = hr0; w[NPT + 3] = hr1;
#pragma unroll
        for (int c = 0; c < NPT; c++) w[c + 2] = p[c];
        float Ap[NPT];
#pragma unroll
        for (int c = 0; c < NPT; c++) Ap[c] = coef * STEN5(w, c) + d[c] * p[c];
        fix_bounds<NPT>(coef, d, p, Ap, isF, isL);
        float pl = 0.f;
#pragma unroll
        for (int c = 0; c < NPT; c++) pl += p[c] * Ap[c];
        float pAp = gred1<GSIZE>(pl, sA, gtid, barId);         // barrier 1
        float a = rs / (pAp + 1e-12f);
        // edge r updates first -> publish halos early (drain under shuffle)
        r[0]       -= a * Ap[0];
        r[1]       -= a * Ap[1];
        r[NPT - 2] -= a * Ap[NPT - 2];
        r[NPT - 1] -= a * Ap[NPT - 1];
        *reinterpret_cast<float2*>(sp + base)           = make_float2(r[0], r[1]);
        *reinterpret_cast<float2*>(sp + base + NPT - 2) = make_float2(r[NPT-2], r[NPT-1]);
#pragma unroll
        for (int c = 2; c < NPT - 2; c++) r[c] -= a * Ap[c];
        float rl2 = 0.f;
#pragma unroll
        for (int c = 0; c < NPT; c++) rl2 += r[c] * r[c];
        float rsnew = gred1<GSIZE>(rl2, sB, gtid, barId);       // barrier 2
#pragma unroll
        for (int c = 0; c < NPT; c++) x[c] += a * p[c];         // hidden by LDS
        if (rsnew < 1e-12f) break;          // == sqrt(rsnew) < 1e-6 (freeze)
        float bta = rsnew / (rs + 1e-12f);
        float2 Ln = *reinterpret_cast<const float2*>(sp + base - 2);
        float2 Rn = *reinterpret_cast<const float2*>(sp + base + NPT);
#pragma unroll
        for (int c = 0; c < NPT; c++) p[c] = r[c] + bta * p[c];
        hl0 = Ln.x + bta * hl0; hl1 = Ln.y + bta * hl1;
        hr0 = Rn.x + bta * hr0; hr1 = Rn.y + bta * hr1;
        rs = rsnew;
    }
}

// fast phase scan on prefetched values: full block, 4 contiguous elems/thread.
__device__ __forceinline__ void fast_phase_v(float4 y4, float ym1, float halfdx,
                                             float* wsum, float ph4[4])
{
    int tid = threadIdx.x;
    int lane = tid & 31, wi = tid >> 5;
    float a0 = (tid > 0) ? (ym1 + y4.x) * halfdx : 0.f;
    float s0 = a0;
    float s1 = s0 + (y4.x + y4.y) * halfdx;
    float s2 = s1 + (y4.y + y4.z) * halfdx;
    float s3 = s2 + (y4.z + y4.w) * halfdx;
    float tot = s3, v = tot;
#pragma unroll
    for (int o = 1; o < 32; o <<= 1) {
        float n = __shfl_up_sync(0xffffffffu, v, o);
        if (lane >= o) v += n;
    }
    __syncthreads();                 // protect wsum reuse across calls
    if (lane == 31) wsum[wi] = v;
    __syncthreads();
    float off = 0.f;
    for (int j = 0; j < wi; j++) off += wsum[j];
    float excl = off + v - tot;
    ph4[0] = TWO_PI_F * (excl + s0);
    ph4[1] = TWO_PI_F * (excl + s1);
    ph4[2] = TWO_PI_F * (excl + s2);
    ph4[3] = TWO_PI_F * (excl + s3);
}

// DSMEM scalar load from cluster rank `rk`
__device__ __forceinline__ float dsmem_ldf(const float* ptr, int rk)
{
    uint32_t a = (uint32_t)__cvta_generic_to_shared(ptr);
    uint32_t ra; float v;
    asm volatile("mapa.shared::cluster.u32 %0, %1, %2;" : "=r"(ra) : "r"(a), "r"(rk));
    asm volatile("ld.shared::cluster.f32 %0, [%1];" : "=f"(v) : "r"(ra) : "memory");
    return v;
}

// ================= ONE fused kernel (cluster of 4 CTAs = one batch) =========
__global__ __launch_bounds__(NT, 1) __cluster_dims__(KK, 1, 1)
void fused_kernel(
    const float* __restrict__ s_in, const float* __restrict__ eIF,
    const float* __restrict__ xm, const float* __restrict__ ym,
    const float* __restrict__ sumx, const float* __restrict__ sumy,
    const float* __restrict__ lam, const int* __restrict__ mask,
    const float* __restrict__ initf,
    const float* __restrict__ alpha_p, const float* __restrict__ beta_p,
    const float* __restrict__ var_p, const float* __restrict__ fs_p,
    const int* __restrict__ iter_p,
    const float* __restrict__ fe_w1, const float* __restrict__ fe_b1,
    const float* __restrict__ fe_w2, const float* __restrict__ fe_b2,
    const float* __restrict__ pr_w1, const float* __restrict__ pr_b1,
    const float* __restrict__ pr_w2, const float* __restrict__ pr_b2,
    const float* __restrict__ pr_w3, const float* __restrict__ pr_b3,
    const float* __restrict__ iw_p,
    float* __restrict__ d_out)
{
    // buffers (raw index [0,NN) at +2; CG views get 2 guard floats each side)
    __shared__ __align__(16) float sraw0[NN + 8];
    __shared__ __align__(16) float sraw1[NN + 8];
    __shared__ __align__(16) float brx[NN];        // rhsx -> xs
    __shared__ __align__(16) float bry[NN];        // rhsy -> ys
    __shared__ __align__(16) float u_buf[NN];
    __shared__ __align__(16) float sredA[2][32];
    __shared__ __align__(16) float sredB[2][32];
    __shared__ float wsum[16];
    __shared__ float m_avg[BB];
    __shared__ float m_h1[BB*32];
    __shared__ float m_z0[BB*18];
    __shared__ float m_z1[BB*64];
    __shared__ float m_z2[BB*32];
    __shared__ float m_res[BB*2];
    __shared__ float m_scal[4];

    float* const sbuf0 = sraw0 + 2;     // element-0 view, 2 guards each side
    float* const sbuf1 = sraw1 + 2;

    const int bk  = blockIdx.x;
    const int b   = bk >> 2;
    const int rk  = bk & 3;          // cluster rank
    const int tid = threadIdx.x;

    // ---------- prefetch all global inputs ----------
    const int base4 = tid * 4;
    const int bbase = b * NN + base4;
    const int rbase = bk * NN + base4;
    const float alpha = *alpha_p, beta = *beta_p;
    const float varv = *var_p, fsv = *fs_p, iw = *iw_p;
    const int it_num = *iter_p;
    const bool act = (mask[bk] != 0);
    float4 sv   = *reinterpret_cast<const float4*>(s_in + bbase);
    float4 sx   = *reinterpret_cast<const float4*>(sumx + bbase);
    float4 sy   = *reinterpret_cast<const float4*>(sumy + bbase);
    float4 lv   = *reinterpret_cast<const float4*>(lam  + bbase);
    float4 eif4 = *reinterpret_cast<const float4*>(eIF  + rbase);
    float  eifm1 = (tid > 0) ? eIF[rbase - 1] : 0.f;
    float4 xm4  = *reinterpret_cast<const float4*>(xm + rbase);
    float4 ym4  = *reinterpret_cast<const float4*>(ym + rbase);
    const int giE = b * NN + rk * QN + tid;     // epilogue gather index
    const float lamE = lam[giE];
    const float sE   = s_in[giE];

    // ---------- MLP (recomputed per CTA; identical everywhere) ----------
    if (tid < BB) {
        const float* f = initf + tid * KK;
        m_avg[tid] = (((f[0] + f[1]) + f[2]) + f[3]) * 0.25f;
    }
    __syncthreads();
    if (tid < 256) {
        int bb = tid >> 5, j = tid & 31;
        m_h1[bb*32 + j] = fmaxf(0.f, m_avg[bb] * fe_w1[j] + fe_b1[j]);
    }
    __syncthreads();
    if (tid < 128) {
        int bb = tid >> 4, j = tid & 15;
        float acc = fe_b2[j];
        for (int e = 0; e < 32; e++) acc += m_h1[bb*32 + e] * fe_w2[j*32 + e];
        m_z0[bb*18 + j] = fmaxf(0.f, acc);
    }
    if (tid < BB) { m_z0[tid*18 + 16] = alpha; m_z0[tid*18 + 17] = beta; }
    __syncthreads();
    {
        int bb = tid >> 6, j = tid & 63;
        float acc = pr_b1[j];
        for (int e = 0; e < 18; e++) acc += m_z0[bb*18 + e] * pr_w1[j*18 + e];
        m_z1[bb*64 + j] = fmaxf(0.f, acc);
    }
    __syncthreads();
    if (tid < 256) {
        int bb = tid >> 5, j = tid & 31;
        float acc = pr_b2[j];
        for (int e = 0; e < 64; e++) acc += m_z1[bb*64 + e] * pr_w2[j*64 + e];
        m_z2[bb*32 + j] = fmaxf(0.f, acc);
    }
    __syncthreads();
    if (tid < 16) {
        int bb = tid >> 1, j = tid & 1;
        float acc = pr_b3[j];
        for (int e = 0; e < 32; e++) acc += m_z2[bb*32 + e] * pr_w3[j*32 + e];
        m_res[bb*2 + j] = tanhf(acc);
    }
    __syncthreads();
    if (tid == 0) {
        float fac = 1.f / (1.f + expf(-iw * (float)it_num));
        float m0 = 0.f, m1 = 0.f;
        for (int bb = 0; bb < BB; bb++) {
            m0 += (m_res[bb*2 + 0] * fac * 0.1f) * alpha;
            m1 += (m_res[bb*2 + 1] * fac * 0.1f) * beta;
        }
        m0 *= 0.125f; m1 *= 0.125f;
        float na = fminf(fmaxf(alpha + m0, 1e-6f), 0.01f);
        float nb = fminf(fmaxf(beta  + m1, 1e-6f), 0.1f);
        double bt = pow(10.0, (double)it_num / 36.0 - 10.0);
        float betathr = fminf((float)bt, nb);
        m_scal[0] = na; m_scal[1] = nb;
        m_scal[2] = 2.f / na; m_scal[3] = 2.f / betathr;
        if (bk == 0) { d_out[OUT_SC + 0] = na; d_out[OUT_SC + 1] = nb; }
    }
    __syncthreads();
    const float na = m_scal[0];
    const float coefA = m_scal[2];
    const float coefS = m_scal[3];
    const float dxf = 1.0f / fsv;
    const float halfdx = 0.5f * dxf;

    // ---------- u = projec5(...) ----------
    float uv[4];
    uv[0] = sv.x - sx.x - sy.x - lv.x / na;
    uv[1] = sv.y - sx.y - sy.y - lv.y / na;
    uv[2] = sv.z - sx.z - sy.z - lv.z / na;
    uv[3] = sv.w - sx.w - sy.w - lv.w / na;
    {
        float loc = uv[0]*uv[0] + uv[1]*uv[1] + uv[2]*uv[2] + uv[3]*uv[3];
        float n2 = gred1<NT>(loc, sredA[0], tid, 0);
        float n = sqrtf(n2);
        float e = sqrtf((float)NN * varv);
        float scale = (n > e) ? (e / fmaxf(n, 1e-30f)) : 1.f;
#pragma unroll
        for (int c = 0; c < 4; c++) { uv[c] *= scale; u_buf[base4 + c] = uv[c]; }
    }

    // ---------- phase + rhs (store to SMEM only) ----------
    {
        float ph4[4];
        fast_phase_v(eif4, eifm1, halfdx, wsum, ph4);
#pragma unroll
        for (int c = 0; c < 4; c++) {
            float ssn, ccs;
            sincosf(ph4[c], &ssn, &ccs);
            float xv = ((const float*)&xm4.x)[c];
            float yv = ((const float*)&ym4.x)[c];
            float resid = ((const float*)&sv.x)[c]
                        - (((const float*)&sx.x)[c] - xv * ccs)
                        - (((const float*)&sy.x)[c] - yv * ssn)
                        - uv[c]
                        - ((const float*)&lv.x)[c] / na;
            sbuf0[base4 + c] = ccs;
            sbuf1[base4 + c] = ssn;
            brx[base4 + c] = ccs * resid;
            bry[base4 + c] = ssn * resid;
        }
    }
    __syncthreads();

    // ---------- concurrent CG for x (warps 0-7) and y (warps 8-15) ----------
    {
        const int grp = tid >> 8;
        const int gtid = tid & 255;
        const int barId = 1 + grp;
        const float* trig = grp ? sbuf1 : sbuf0;
        const float* rh   = grp ? bry   : brx;
        const float* x0g  = (grp ? ym : xm) + bk * NN;
        float* sp         = grp ? sbuf1 : sbuf0;        // halo-exchange view
        float* outb       = grp ? bry : brx;

        float d8[8], rhs8[8], x8[8];
#pragma unroll
        for (int c = 0; c < 8; c++) {
            int i = gtid * 8 + c;
            float t = trig[i];
            d8[c] = t * t + 1e-6f;
            rhs8[c] = rh[i];
            x8[c] = x0g[i];
        }
        cg_solve<256, 8>(gtid, barId, coefA, d8, x8, rhs8, sp,
                         sredA[grp], sredB[grp], false);
        // write result over rhs buffer (only this group reads/writes it)
        barx<256>(barId);
#pragma unroll
        for (int c = 0; c < 8; c++) outb[gtid * 8 + c] = x8[c];
    }
    __syncthreads();

    // ---------- deltaIF + smooth CG ----------
    float xv4[4], yv4[4], x4[4];
    {
        float rhs4[4], d4[4];
#pragma unroll
        for (int c = 0; c < 4; c++) {
            int i = base4 + c;
            float xb, yb;
            if (i == 0) {
                xb = (brx[1] - brx[0]) / dxf;
                yb = (bry[1] - bry[0]) / dxf;
            } else if (i == NN - 1) {
                xb = (brx[NN-1] - brx[NN-2]) / dxf;
                yb = (bry[NN-1] - bry[NN-2]) / dxf;
            } else {
                xb = (brx[i+1] - brx[i-1]) / (2.0f * dxf);
                yb = (bry[i+1] - bry[i-1]) / (2.0f * dxf);
            }
            xv4[c] = brx[i]; yv4[c] = bry[i];
            float denom = xv4[c]*xv4[c] + yv4[c]*yv4[c] + 1e-12f;
            rhs4[c] = (xv4[c] * yb - yv4[c] * xb) / (denom * TWO_PI_F);
            d4[c] = 1.0f + 1e-6f;
            x4[c] = 0.f;
        }
        cg_solve<NT, 4>(tid, 0, coefS, d4, x4, rhs4, sbuf0,
                        sredA[0], sredB[0], true);
    }

    // ---------- outputs eIF/xm/ym + stash new_eIF for phase scan ----------
    float ne4[4];
#pragma unroll
    for (int c = 0; c < 4; c++) {
        int i = base4 + c;
        int gi = bk * NN + i;
        float e = ((const float*)&eif4.x)[c];
        ne4[c] = act ? (e - 0.5f * x4[c]) : e;
        d_out[OUT_EIF + gi] = ne4[c];
        d_out[OUT_XM  + gi] = act ? xv4[c] : ((const float*)&xm4.x)[c];
        d_out[OUT_YM  + gi] = act ? yv4[c] : ((const float*)&ym4.x)[c];
        sbuf1[i] = ne4[c];
    }
    __syncthreads();

    // ---------- new phase + masked contributions into SMEM ----------
    {
        float nem1 = (tid > 0) ? sbuf1[base4 - 1] : 0.f;
        float4 ne = make_float4(ne4[0], ne4[1], ne4[2], ne4[3]);
        float ph4[4];
        fast_phase_v(ne, nem1, halfdx, wsum, ph4);
        float cx[4], cy[4];
#pragma unroll
        for (int c = 0; c < 4; c++) {
            float ssn, ccs;
            sincosf(ph4[c], &ssn, &ccs);
            cx[c] = act ? xv4[c] * ccs : 0.f;
            cy[c] = act ? yv4[c] * ssn : 0.f;
        }
        __syncthreads();        // all reads of sbuf1 (nem1) complete
#pragma unroll
        for (int c = 0; c < 4; c++) {
            sbuf0[base4 + c] = cx[c];
            sbuf1[base4 + c] = cy[c];
        }
    }

    // ---------- cluster gather: bsx/bsy + lamuda ----------
    asm volatile("barrier.cluster.arrive.aligned;" ::: "memory");
    asm volatile("barrier.cluster.wait.aligned;"   ::: "memory");
    {
        int i = rk * QN + tid;
        float bsx = 0.f, bsy = 0.f;
#pragma unroll
        for (int k = 0; k < KK; k++) {
            bsx += dsmem_ldf(&sbuf0[i], k);
            bsy += dsmem_ldf(&sbuf1[i], k);
        }
        int gi = b * NN + i;
        d_out[OUT_BSX + gi] = bsx;
        d_out[OUT_BSY + gi] = bsy;
        d_out[OUT_LAM + gi] = lamE + na * (u_buf[i] + bsx + bsy - sE);
    }
    asm volatile("barrier.cluster.arrive.aligned;" ::: "memory");
    asm volatile("barrier.cluster.wait.aligned;"   ::: "memory");
}

// ---------------- launch ---------------------------------------------------
extern "C" void kernel_launch(void* const* d_in, const int* in_sizes, int n_in,
                              void* d_out_v, int out_size)
{
    const float* s      = (const float*)d_in[0];
    const float* eIF    = (const float*)d_in[1];
    const float* xm     = (const float*)d_in[2];
    const float* ym     = (const float*)d_in[3];
    const float* sum_x  = (const float*)d_in[4];
    const float* sum_y  = (const float*)d_in[5];
    const float* lamuda = (const float*)d_in[6];
    const float* initf  = (const float*)d_in[7];
    const int*   mmask  = (const int*)  d_in[8];
    const float* alpha  = (const float*)d_in[9];
    const float* beta   = (const float*)d_in[10];
    const float* var    = (const float*)d_in[11];
    const float* fs     = (const float*)d_in[12];
    const int*   iter   = (const int*)  d_in[13];
    const float* fe_w1  = (const float*)d_in[14];
    const float* fe_b1  = (const float*)d_in[15];
    const float* fe_w2  = (const float*)d_in[16];
    const float* fe_b2  = (const float*)d_in[17];
    const float* pr_w1  = (const float*)d_in[18];
    const float* pr_b1  = (const float*)d_in[19];
    const float* pr_w2  = (const float*)d_in[20];
    const float* pr_b2  = (const float*)d_in[21];
    const float* pr_w3  = (const float*)d_in[22];
    const float* pr_b3  = (const float*)d_in[23];
    const float* iw     = (const float*)d_in[24];
    float* d_out = (float*)d_out_v;

    fused_kernel<<<BK, NT>>>(s, eIF, xm, ym, sum_x, sum_y, lamuda, mmask,
                             initf, alpha, beta, var, fs, iter,
                             fe_w1, fe_b1, fe_w2, fe_b2,
                             pr_w1, pr_b1, pr_w2, pr_b2, pr_w3, pr_b3,
                             iw, d_out);
}

// round 9
// speedup vs baseline: 1.0798x; 1.0584x over previous
#include <cuda_runtime.h>
#include <math.h>
#include <stdint.h>

// ---------------- problem constants ----------------
#define NN   2048
#define NT   512
#define BB   8
#define KK   4
#define CL   8                  // cluster size: 4 modes x {x,y}
#define NGRID (BB * CL)         // 64 CTAs
#define EN   (NN / CL)          // 256 elements per rank in epilogue gather
#define TWO_PI_F 6.283185307179586f

// output layout (flattened tuple, fp32)
#define OUT_EIF 0
#define OUT_XM  65536
#define OUT_YM  131072
#define OUT_BSX 196608
#define OUT_BSY 212992
#define OUT_LAM 229376
#define OUT_SC  245760

// block-wide reduce: 4 shuffles (16-lane groups) -> 32 partials -> 1 barrier
__device__ __forceinline__ float bred(float v, float* sred, int tid)
{
#pragma unroll
    for (int o = 8; o > 0; o >>= 1) v += __shfl_down_sync(0xffffffffu, v, o);
    if ((tid & 15) == 0) sred[tid >> 4] = v;
    __syncthreads();
    float s = 0.f;
#pragma unroll
    for (int j = 0; j < 8; j++) {
        float4 q = reinterpret_cast<float4*>(sred)[j];
        s += (q.x + q.y) + (q.z + q.w);
    }
    return s;
}

// interior 5-point stencil of (D^T D): [1,-4,6,-4,1]; w[k] = elem(base-2+k)
#define STEN5(w, c) ((w)[c] - 4.f*(w)[(c)+1] + 6.f*(w)[(c)+2] - 4.f*(w)[(c)+3] + (w)[(c)+4])

// Boundary rows, exact reference expressions, recomputed on edge threads only.
__device__ __forceinline__ void fix_bounds4(float coef, const float* d,
                                            const float* v, float* Av,
                                            bool isF, bool isL)
{
    if (isF) {
        Av[0] = coef * (2.f*v[0] - 3.f*v[1] + v[2]) + d[0]*v[0];
        Av[1] = coef * (-3.f*v[0] + 6.f*v[1] - 4.f*v[2] + v[3]) + d[1]*v[1];
    }
    if (isL) {
        Av[2] = coef * (v[0] - 4.f*v[1] + 6.f*v[2] - 3.f*v[3]) + d[2]*v[2];
        Av[3] = coef * (v[1] - 3.f*v[2] + 2.f*v[3]) + d[3]*v[3];
    }
}

// 512-thread CG, NPT=4, reference semantics: explicit rsnew = ||r-a*Ap||^2,
// freeze == break. p in registers; r halos via SMEM float2; neighbor p halos
// reconstructed as r_halo + beta*p_halo_old. sp = element-0 view with 2 guard
// floats each side (zeroed; never used by boundary math). 2 barriers/iter.
__device__ __forceinline__ void cg_solve4(int tid, float coef,
        const float* d, float* x, const float* rhs,
        float* sp, float* sA, float* sB, bool x0_zero)
{
    const int base = tid * 4;
    const bool isF = (tid == 0);
    const bool isL = (tid == NT - 1);
    float r[4], p[4];
    float rl = 0.f;

    __syncthreads();                       // prior readers of sp region done
    if (isF) *reinterpret_cast<float2*>(sp - 2)  = make_float2(0.f, 0.f);
    if (isL) *reinterpret_cast<float2*>(sp + NN) = make_float2(0.f, 0.f);

    if (x0_zero) {
#pragma unroll
        for (int c = 0; c < 4; c++) { r[c] = rhs[c]; rl += r[c] * r[c]; }
    } else {
        *reinterpret_cast<float2*>(sp + base)     = make_float2(x[0], x[1]);
        *reinterpret_cast<float2*>(sp + base + 2) = make_float2(x[2], x[3]);
        __syncthreads();
        float2 L = *reinterpret_cast<const float2*>(sp + base - 2);
        float2 R = *reinterpret_cast<const float2*>(sp + base + 4);
        float w[8];
        w[0] = L.x; w[1] = L.y; w[6] = R.x; w[7] = R.y;
#pragma unroll
        for (int c = 0; c < 4; c++) w[c + 2] = x[c];
        float Ax[4];
#pragma unroll
        for (int c = 0; c < 4; c++) Ax[c] = coef * STEN5(w, c) + d[c] * x[c];
        fix_bounds4(coef, d, x, Ax, isF, isL);
#pragma unroll
        for (int c = 0; c < 4; c++) { r[c] = rhs[c] - Ax[c]; rl += r[c] * r[c]; }
        __syncthreads();                   // x-halo reads done before overwrite
    }
    *reinterpret_cast<float2*>(sp + base)     = make_float2(r[0], r[1]);
    *reinterpret_cast<float2*>(sp + base + 2) = make_float2(r[2], r[3]);
    float rs = bred(rl, sB, tid);
    float2 Li = *reinterpret_cast<const float2*>(sp + base - 2);
    float2 Ri = *reinterpret_cast<const float2*>(sp + base + 4);
    float hl0 = Li.x, hl1 = Li.y, hr0 = Ri.x, hr1 = Ri.y;
#pragma unroll
    for (int c = 0; c < 4; c++) p[c] = r[c];

    for (int it = 0; it < 30; it++) {
        float w[8];
        w[0] = hl0; w[1] = hl1; w[6] = hr0; w[7] = hr1;
#pragma unroll
        for (int c = 0; c < 4; c++) w[c + 2] = p[c];
        float Ap[4];
#pragma unroll
        for (int c = 0; c < 4; c++) Ap[c] = coef * STEN5(w, c) + d[c] * p[c];
        fix_bounds4(coef, d, p, Ap, isF, isL);
        float pl = 0.f;
#pragma unroll
        for (int c = 0; c < 4; c++) pl += p[c] * Ap[c];
        float pAp = bred(pl, sA, tid);                          // barrier 1
        float a = rs / (pAp + 1e-12f);
        float rl2 = 0.f;
#pragma unroll
        for (int c = 0; c < 4; c++) { r[c] -= a * Ap[c]; rl2 += r[c] * r[c]; }
        *reinterpret_cast<float2*>(sp + base)     = make_float2(r[0], r[1]);
        *reinterpret_cast<float2*>(sp + base + 2) = make_float2(r[2], r[3]);
        float rsnew = bred(rl2, sB, tid);                       // barrier 2
#pragma unroll
        for (int c = 0; c < 4; c++) x[c] += a * p[c];           // hidden by LDS
        if (rsnew < 1e-12f) break;          // == sqrt(rsnew) < 1e-6 (freeze)
        float bta = rsnew / (rs + 1e-12f);
        float2 Ln = *reinterpret_cast<const float2*>(sp + base - 2);
        float2 Rn = *reinterpret_cast<const float2*>(sp + base + 4);
#pragma unroll
        for (int c = 0; c < 4; c++) p[c] = r[c] + bta * p[c];
        hl0 = Ln.x + bta * hl0; hl1 = Ln.y + bta * hl1;
        hr0 = Rn.x + bta * hr0; hr1 = Rn.y + bta * hr1;
        rs = rsnew;
    }
}

// fast phase scan on prefetched values: full block, 4 contiguous elems/thread.
__device__ __forceinline__ void fast_phase_v(float4 y4, float ym1, float halfdx,
                                             float* wsum, float ph4[4])
{
    int tid = threadIdx.x;
    int lane = tid & 31, wi = tid >> 5;
    float a0 = (tid > 0) ? (ym1 + y4.x) * halfdx : 0.f;
    float s0 = a0;
    float s1 = s0 + (y4.x + y4.y) * halfdx;
    float s2 = s1 + (y4.y + y4.z) * halfdx;
    float s3 = s2 + (y4.z + y4.w) * halfdx;
    float tot = s3, v = tot;
#pragma unroll
    for (int o = 1; o < 32; o <<= 1) {
        float n = __shfl_up_sync(0xffffffffu, v, o);
        if (lane >= o) v += n;
    }
    __syncthreads();                 // protect wsum reuse across calls
    if (lane == 31) wsum[wi] = v;
    __syncthreads();
    float off = 0.f;
    for (int j = 0; j < wi; j++) off += wsum[j];
    float excl = off + v - tot;
    ph4[0] = TWO_PI_F * (excl + s0);
    ph4[1] = TWO_PI_F * (excl + s1);
    ph4[2] = TWO_PI_F * (excl + s2);
    ph4[3] = TWO_PI_F * (excl + s3);
}

// DSMEM scalar load from cluster rank `rk`
__device__ __forceinline__ float dsmem_ldf(const float* ptr, int rk)
{
    uint32_t a = (uint32_t)__cvta_generic_to_shared(ptr);
    uint32_t ra; float v;
    asm volatile("mapa.shared::cluster.u32 %0, %1, %2;" : "=r"(ra) : "r"(a), "r"(rk));
    asm volatile("ld.shared::cluster.f32 %0, [%1];" : "=f"(v) : "r"(ra) : "memory");
    return v;
}

__device__ __forceinline__ void cluster_sync_()
{
    asm volatile("barrier.cluster.arrive.aligned;" ::: "memory");
    asm volatile("barrier.cluster.wait.aligned;"   ::: "memory");
}

// ====== ONE fused kernel: cluster of 8 CTAs = one batch (4 modes x {x,y}) ===
__global__ __launch_bounds__(NT, 1) __cluster_dims__(CL, 1, 1)
void fused_kernel(
    const float* __restrict__ s_in, const float* __restrict__ eIF,
    const float* __restrict__ xm, const float* __restrict__ ym,
    const float* __restrict__ sumx, const float* __restrict__ sumy,
    const float* __restrict__ lam, const int* __restrict__ mask,
    const float* __restrict__ initf,
    const float* __restrict__ alpha_p, const float* __restrict__ beta_p,
    const float* __restrict__ var_p, const float* __restrict__ fs_p,
    const int* __restrict__ iter_p,
    const float* __restrict__ fe_w1, const float* __restrict__ fe_b1,
    const float* __restrict__ fe_w2, const float* __restrict__ fe_b2,
    const float* __restrict__ pr_w1, const float* __restrict__ pr_b1,
    const float* __restrict__ pr_w2, const float* __restrict__ pr_b2,
    const float* __restrict__ pr_w3, const float* __restrict__ pr_b3,
    const float* __restrict__ iw_p,
    float* __restrict__ d_out)
{
    __shared__ __align__(16) float sraw0[NN + 8];  // CG workspace -> contribution
    __shared__ __align__(16) float sraw1[NN + 8];  // new_eIF stash
    __shared__ __align__(16) float own[NN];        // own CG solution
    __shared__ __align__(16) float peer[NN];       // peer CG solution (DSMEM copy)
    __shared__ __align__(16) float u_buf[NN];
    __shared__ __align__(16) float sredA[32];
    __shared__ __align__(16) float sredB[32];
    __shared__ float wsum[16];
    __shared__ float m_avg[BB];
    __shared__ float m_h1[BB*32];
    __shared__ float m_z0[BB*18];
    __shared__ float m_z1[BB*64];
    __shared__ float m_z2[BB*32];
    __shared__ float m_res[BB*2];
    __shared__ float m_scal[4];

    float* const sbuf0 = sraw0 + 2;     // element-0 view, 2 guards each side
    float* const sbuf1 = sraw1 + 2;

    const int bkid = blockIdx.x;
    const int b     = bkid >> 3;        // batch
    const int rk    = bkid & 7;         // cluster rank
    const int kmode = rk >> 1;          // mode 0..3
    const int which = rk & 1;           // 0 = x-solve, 1 = y-solve
    const int tid = threadIdx.x;

    // ---------- prefetch all global inputs ----------
    const int base4 = tid * 4;
    const int bbase = b * NN + base4;
    const int mb    = (b * KK + kmode) * NN;       // this mode's row base
    const int rbase = mb + base4;
    const float alpha = *alpha_p, beta = *beta_p;
    const float varv = *var_p, fsv = *fs_p, iw = *iw_p;
    const int it_num = *iter_p;
    const bool act = (mask[b * KK + kmode] != 0);
    float4 sv   = *reinterpret_cast<const float4*>(s_in + bbase);
    float4 sx   = *reinterpret_cast<const float4*>(sumx + bbase);
    float4 sy   = *reinterpret_cast<const float4*>(sumy + bbase);
    float4 lv   = *reinterpret_cast<const float4*>(lam  + bbase);
    float4 eif4 = *reinterpret_cast<const float4*>(eIF  + rbase);
    float  eifm1 = (tid > 0) ? eIF[rbase - 1] : 0.f;
    float4 xm4  = *reinterpret_cast<const float4*>(xm + rbase);
    float4 ym4  = *reinterpret_cast<const float4*>(ym + rbase);
    float lamE = 0.f, sE = 0.f;
    const int giE = b * NN + rk * EN + (tid & (EN - 1));
    if (tid < EN) { lamE = lam[giE]; sE = s_in[giE]; }

    // ---------- MLP (recomputed per CTA; identical everywhere) ----------
    if (tid < BB) {
        const float* f = initf + tid * KK;
        m_avg[tid] = (((f[0] + f[1]) + f[2]) + f[3]) * 0.25f;
    }
    __syncthreads();
    if (tid < 256) {
        int bb = tid >> 5, j = tid & 31;
        m_h1[bb*32 + j] = fmaxf(0.f, m_avg[bb] * fe_w1[j] + fe_b1[j]);
    }
    __syncthreads();
    if (tid < 128) {
        int bb = tid >> 4, j = tid & 15;
        float acc = fe_b2[j];
        for (int e = 0; e < 32; e++) acc += m_h1[bb*32 + e] * fe_w2[j*32 + e];
        m_z0[bb*18 + j] = fmaxf(0.f, acc);
    }
    if (tid < BB) { m_z0[tid*18 + 16] = alpha; m_z0[tid*18 + 17] = beta; }
    __syncthreads();
    {
        int bb = tid >> 6, j = tid & 63;
        float acc = pr_b1[j];
        for (int e = 0; e < 18; e++) acc += m_z0[bb*18 + e] * pr_w1[j*18 + e];
        m_z1[bb*64 + j] = fmaxf(0.f, acc);
    }
    __syncthreads();
    if (tid < 256) {
        int bb = tid >> 5, j = tid & 31;
        float acc = pr_b2[j];
        for (int e = 0; e < 64; e++) acc += m_z1[bb*64 + e] * pr_w2[j*64 + e];
        m_z2[bb*32 + j] = fmaxf(0.f, acc);
    }
    __syncthreads();
    if (tid < 16) {
        int bb = tid >> 1, j = tid & 1;
        float acc = pr_b3[j];
        for (int e = 0; e < 32; e++) acc += m_z2[bb*32 + e] * pr_w3[j*32 + e];
        m_res[bb*2 + j] = tanhf(acc);
    }
    __syncthreads();
    if (tid == 0) {
        float fac = 1.f / (1.f + expf(-iw * (float)it_num));
        float m0 = 0.f, m1 = 0.f;
        for (int bb = 0; bb < BB; bb++) {
            m0 += (m_res[bb*2 + 0] * fac * 0.1f) * alpha;
            m1 += (m_res[bb*2 + 1] * fac * 0.1f) * beta;
        }
        m0 *= 0.125f; m1 *= 0.125f;
        float na = fminf(fmaxf(alpha + m0, 1e-6f), 0.01f);
        float nb = fminf(fmaxf(beta  + m1, 1e-6f), 0.1f);
        double bt = pow(10.0, (double)it_num / 36.0 - 10.0);
        float betathr = fminf((float)bt, nb);
        m_scal[0] = na; m_scal[1] = nb;
        m_scal[2] = 2.f / na; m_scal[3] = 2.f / betathr;
        if (bkid == 0) { d_out[OUT_SC + 0] = na; d_out[OUT_SC + 1] = nb; }
    }
    __syncthreads();
    const float na = m_scal[0];
    const float coefA = m_scal[2];
    const float coefS = m_scal[3];
    const float dxf = 1.0f / fsv;
    const float halfdx = 0.5f * dxf;

    // ---------- u = projec5(...) ----------
    float uv[4];
    uv[0] = sv.x - sx.x - sy.x - lv.x / na;
    uv[1] = sv.y - sx.y - sy.y - lv.y / na;
    uv[2] = sv.z - sx.z - sy.z - lv.z / na;
    uv[3] = sv.w - sx.w - sy.w - lv.w / na;
    {
        float loc = uv[0]*uv[0] + uv[1]*uv[1] + uv[2]*uv[2] + uv[3]*uv[3];
        float n2 = bred(loc, sredA, tid);
        float n = sqrtf(n2);
        float e = sqrtf((float)NN * varv);
        float scale = (n > e) ? (e / fmaxf(n, 1e-30f)) : 1.f;
#pragma unroll
        for (int c = 0; c < 4; c++) { uv[c] *= scale; u_buf[base4 + c] = uv[c]; }
    }

    // ---------- phase + rhs/diag/x0 (all in registers) ----------
    float d4[4], rhs4[4], x4[4];
    {
        float ph4[4];
        fast_phase_v(eif4, eifm1, halfdx, wsum, ph4);
#pragma unroll
        for (int c = 0; c < 4; c++) {
            float ssn, ccs;
            sincosf(ph4[c], &ssn, &ccs);
            float xv = ((const float*)&xm4.x)[c];
            float yv = ((const float*)&ym4.x)[c];
            float resid = ((const float*)&sv.x)[c]
                        - (((const float*)&sx.x)[c] - xv * ccs)
                        - (((const float*)&sy.x)[c] - yv * ssn)
                        - uv[c]
                        - ((const float*)&lv.x)[c] / na;
            float t = which ? ssn : ccs;
            d4[c] = t * t + 1e-6f;
            rhs4[c] = t * resid;
            x4[c] = which ? yv : xv;
        }
    }

    // ---------- this CTA's CG solve (x OR y system) ----------
    cg_solve4(tid, coefA, d4, x4, rhs4, sbuf0, sredA, sredB, false);
#pragma unroll
    for (int c = 0; c < 4; c++) own[base4 + c] = x4[c];
    __syncthreads();

    // ---------- exchange with paired CTA (rank ^ 1) via DSMEM ----------
    cluster_sync_();
    {
        const int prk = rk ^ 1;
#pragma unroll
        for (int c = 0; c < 4; c++)
            peer[base4 + c] = dsmem_ldf(&own[base4 + c], prk);
    }
    const float* xsP = which ? peer : own;
    const float* ysP = which ? own : peer;

    // ---------- deltaIF + smooth CG (duplicated across the pair) ----------
    float sx4[4];
    {
        float srhs[4], sd[4];
        __syncthreads();       // peer[] fully written before neighbor reads
#pragma unroll
        for (int c = 0; c < 4; c++) {
            int i = base4 + c;
            float xb, yb;
            if (i == 0) {
                xb = (xsP[1] - xsP[0]) / dxf;
                yb = (ysP[1] - ysP[0]) / dxf;
            } else if (i == NN - 1) {
                xb = (xsP[NN-1] - xsP[NN-2]) / dxf;
                yb = (ysP[NN-1] - ysP[NN-2]) / dxf;
            } else {
                xb = (xsP[i+1] - xsP[i-1]) / (2.0f * dxf);
                yb = (ysP[i+1] - ysP[i-1]) / (2.0f * dxf);
            }
            float xv = xsP[i], yv = ysP[i];
            float denom = xv * xv + yv * yv + 1e-12f;
            srhs[c] = (xv * yb - yv * xb) / (denom * TWO_PI_F);
            sd[c] = 1.0f + 1e-6f;
            sx4[c] = 0.f;
        }
        cg_solve4(tid, coefS, sd, sx4, srhs, sbuf0, sredA, sredB, true);
    }

    // ---------- outputs eIF/xm(/ym) + stash new_eIF ----------
    float ne4[4];
#pragma unroll
    for (int c = 0; c < 4; c++) {
        int i = base4 + c;
        int gi = mb + i;
        float e = ((const float*)&eif4.x)[c];
        ne4[c] = act ? (e - 0.5f * sx4[c]) : e;
        if (which == 0) {
            d_out[OUT_EIF + gi] = ne4[c];
            d_out[OUT_XM  + gi] = act ? xsP[i] : ((const float*)&xm4.x)[c];
        } else {
            d_out[OUT_YM  + gi] = act ? ysP[i] : ((const float*)&ym4.x)[c];
        }
        sbuf1[i] = ne4[c];
    }
    __syncthreads();

    // ---------- new phase + masked contribution into sbuf0 ----------
    {
        float nem1 = (tid > 0) ? sbuf1[base4 - 1] : 0.f;
        float4 ne = make_float4(ne4[0], ne4[1], ne4[2], ne4[3]);
        float ph4[4];
        fast_phase_v(ne, nem1, halfdx, wsum, ph4);
        float cc[4];
#pragma unroll
        for (int c = 0; c < 4; c++) {
            float ssn, ccs;
            sincosf(ph4[c], &ssn, &ccs);
            int i = base4 + c;
            cc[c] = act ? (which ? ysP[i] * ssn : xsP[i] * ccs) : 0.f;
        }
        __syncthreads();
#pragma unroll
        for (int c = 0; c < 4; c++) sbuf0[base4 + c] = cc[c];
    }

    // ---------- cluster gather: bsx/bsy + lamuda ----------
    cluster_sync_();
    if (tid < EN) {
        int i = rk * EN + tid;
        float bsx = 0.f, bsy = 0.f;
#pragma unroll
        for (int k = 0; k < KK; k++) {
            bsx += dsmem_ldf(&sbuf0[i], 2 * k);
            bsy += dsmem_ldf(&sbuf0[i], 2 * k + 1);
        }
        d_out[OUT_BSX + giE] = bsx;
        d_out[OUT_BSY + giE] = bsy;
        d_out[OUT_LAM + giE] = lamE + na * (u_buf[i] + bsx + bsy - sE);
    }
    cluster_sync_();
}

// ---------------- launch ---------------------------------------------------
extern "C" void kernel_launch(void* const* d_in, const int* in_sizes, int n_in,
                              void* d_out_v, int out_size)
{
    const float* s      = (const float*)d_in[0];
    const float* eIF    = (const float*)d_in[1];
    const float* xm     = (const float*)d_in[2];
    const float* ym     = (const float*)d_in[3];
    const float* sum_x  = (const float*)d_in[4];
    const float* sum_y  = (const float*)d_in[5];
    const float* lamuda = (const float*)d_in[6];
    const float* initf  = (const float*)d_in[7];
    const int*   mmask  = (const int*)  d_in[8];
    const float* alpha  = (const float*)d_in[9];
    const float* beta   = (const float*)d_in[10];
    const float* var    = (const float*)d_in[11];
    const float* fs     = (const float*)d_in[12];
    const int*   iter   = (const int*)  d_in[13];
    const float* fe_w1  = (const float*)d_in[14];
    const float* fe_b1  = (const float*)d_in[15];
    const float* fe_w2  = (const float*)d_in[16];
    const float* fe_b2  = (const float*)d_in[17];
    const float* pr_w1  = (const float*)d_in[18];
    const float* pr_b1  = (const float*)d_in[19];
    const float* pr_w2  = (const float*)d_in[20];
    const float* pr_b2  = (const float*)d_in[21];
    const float* pr_w3  = (const float*)d_in[22];
    const float* pr_b3  = (const float*)d_in[23];
    const float* iw     = (const float*)d_in[24];
    float* d_out = (float*)d_out_v;

    fused_kernel<<<NGRID, NT>>>(s, eIF, xm, ym, sum_x, sum_y, lamuda, mmask,
                                initf, alpha, beta, var, fs, iter,
                                fe_w1, fe_b1, fe_w2, fe_b2,
                                pr_w1, pr_b1, pr_w2, pr_b2, pr_w3, pr_b3,
                                iw, d_out);
}